// round 14
// baseline (speedup 1.0000x reference)
#include <cuda_runtime.h>
#include <cuda_fp16.h>
#include <cstdint>

// Problem dims
#define S_LEN 1024
#define B_DIM 256
#define E_DIM 128
#define H_DIM 256
#define O_DIM 2
#define K_DIM (E_DIM + H_DIM)   // 384

// Decomposition: 8 batch groups x 16 hidden groups = 128 CTAs (1 per SM)
#define GB 8
#define GC 16
#define NCTA (GB * GC)
#define BT (B_DIM / GB)          // 32 batch rows per CTA
#define HS (H_DIM / GC)          // 16 hidden units per CTA
#define GT (4 * HS)              // 64 gate columns per CTA
#define NTHR 512                 // 16 warps: 2 m16 tiles x 8 n8 groups

// fp16 GEMM, no k-split: each warp does m16 x n8, full K (24 k16 tiles)
#define NKT 24
#define NXT 8                    // x-part k16 tiles (emb, k<128)

// Hidden-state ring depth (producer/consumer slack)
#define HD 4

// Strides
#define WT_ST 72                 // f32 weight [k][col] (init only)
#define ACT_STH 392              // sA row stride in halves (2-wavefront LDS.64 banking)
#define ACT_STB (ACT_STH * 2)    // 784 bytes

// SMEM byte layout
#define OFF_W    0
#define OFF_A    (OFF_W + K_DIM * WT_ST * 4)
#define OFF_LEN  (OFF_A + BT * ACT_STB)
#define OFF_TOK  (OFF_LEN + BT * 4)
#define OFF_MAX  (OFF_TOK + BT * 4)
#define OFF_RDY  (OFF_MAX + 16)
#define OFF_CONS (OFF_RDY + 64)
#define SMEM_BYTES (OFF_CONS + 64)
static_assert(SMEM_BYTES <= 227 * 1024, "smem too big");

// Global scratch: ring-buffered hidden state, fp16, pair-permuted columns
__device__ __half g_h[HD][B_DIM][H_DIM];
// Init/final barrier (monotonic gen, replay-safe)
__device__ unsigned g_cnt[GB][32];
__device__ unsigned g_gen[GB][32];
// Dataflow flags: per-CTA monotonic counters, one 128B line each (R11 protocol)
__device__ unsigned g_ready[GB][GC][32];
__device__ unsigned g_cons[GB][GC][32];

// Pair permutation within each 16-col group: (col 2d,2d+1)+(2d+8,2d+9) adjacent -> LDS.64
__device__ __forceinline__ int perm16(int c) {
    int u = (c & 15) >> 1;
    int p = 2 * (u & 3) + (u >> 2);
    return (c & ~15) + 2 * p + (c & 1);
}

__device__ __forceinline__ float sigf(float x) {
    return __fdividef(1.0f, 1.0f + __expf(-x));
}
__device__ __forceinline__ float tanhfast(float x) {
    return 2.0f * __fdividef(1.0f, 1.0f + __expf(-2.0f * x)) - 1.0f;
}
__device__ __forceinline__ unsigned packh2(float a, float b) {
    __half2 h = __floats2half2_rn(a, b);
    return *reinterpret_cast<unsigned*>(&h);
}

__device__ __forceinline__ void mma16(float& d0, float& d1, float& d2, float& d3,
                                      unsigned a0, unsigned a1, unsigned a2, unsigned a3,
                                      unsigned b0, unsigned b1) {
    asm volatile(
        "mma.sync.aligned.m16n8k16.row.col.f32.f16.f16.f32 "
        "{%0,%1,%2,%3},{%4,%5,%6,%7},{%8,%9},{%0,%1,%2,%3};"
        : "+f"(d0), "+f"(d1), "+f"(d2), "+f"(d3)
        : "r"(a0), "r"(a1), "r"(a2), "r"(a3), "r"(b0), "r"(b1));
}

#define CP_ASYNC16(dst_u32, src) \
    asm volatile("cp.async.cg.shared.global [%0], [%1], 16;" :: "r"(dst_u32), "l"(src))
#define CP_COMMIT() asm volatile("cp.async.commit_group;")
#define CP_WAIT0()  asm volatile("cp.async.wait_group 0;")

__device__ __forceinline__ unsigned ld_acq(const unsigned* p) {
    unsigned v;
    asm volatile("ld.acquire.gpu.global.u32 %0, [%1];" : "=r"(v) : "l"(p) : "memory");
    return v;
}
__device__ __forceinline__ void st_rel(unsigned* p, unsigned v) {
    asm volatile("st.release.gpu.global.u32 [%0], %1;" :: "l"(p), "r"(v) : "memory");
}

__device__ __forceinline__ void gbar_arrive(int gb, unsigned target) {
    unsigned old;
    asm volatile("atom.acq_rel.gpu.global.add.u32 %0, [%1], %2;"
                 : "=r"(old) : "l"(&g_cnt[gb][0]), "r"(1u) : "memory");
    if (old == GC - 1u) {
        asm volatile("st.relaxed.gpu.global.u32 [%0], %1;" :: "l"(&g_cnt[gb][0]), "r"(0u) : "memory");
        st_rel(&g_gen[gb][0], target);
    }
}
__device__ __forceinline__ void gbar_wait(int gb, unsigned target) {
    while ((int)(ld_acq(&g_gen[gb][0]) - target) < 0) {}
}

__global__ void __launch_bounds__(NTHR, 1)
lstm_kernel(const int* __restrict__ inp, const int* __restrict__ lengths,
            const float* __restrict__ h0, const float* __restrict__ c0,
            const float* __restrict__ emb, const float* __restrict__ w_ih,
            const float* __restrict__ w_hh, const float* __restrict__ b_ih,
            const float* __restrict__ b_hh, const float* __restrict__ dec_w,
            float* __restrict__ out) {
    extern __shared__ char smc[];
    float*    sW    = (float*)(smc + OFF_W);      // [K_DIM][WT_ST] f32, init only
    __half*   sAh   = (__half*)(smc + OFF_A);     // [BT][ACT_STH]: emb 0..127, h 128..383
    int*      sLen  = (int*)(smc + OFF_LEN);      // [BT]
    int*      sTok  = (int*)(smc + OFF_TOK);      // [BT]
    int*      sMax  = (int*)(smc + OFF_MAX);      // [1]
    unsigned* sRdyBase  = (unsigned*)(smc + OFF_RDY);   // [16]
    unsigned* sConsBase = (unsigned*)(smc + OFF_CONS);  // [16]

    const int tid = threadIdx.x;
    const int cta = blockIdx.x;
    const int gb = cta / GC;
    const int gc = cta % GC;
    const int b0 = gb * BT;

    // --- entry sampling (race-free before the init barrier) ---
    unsigned gen0 = 0;
    if (tid == 0) gen0 = ld_acq(&g_gen[gb][0]);
    if (tid < GC) {
        sRdyBase[tid]  = ld_acq(&g_ready[gb][tid][0]);
        sConsBase[tid] = ld_acq(&g_cons[gb][tid][0]);
    }

    // ---- one-time init ----
    // Weight columns GATE-INTERLEAVED: col = 4*unit_local + gate (i,f,g,o)
    for (int idx = tid; idx < K_DIM * GT; idx += NTHR) {
        int k = idx / GT, c = idx % GT;
        int unit = c >> 2, gate = c & 3;
        int grow = gate * H_DIM + gc * HS + unit;
        float w = (k < E_DIM) ? w_ih[grow * E_DIM + k] : w_hh[grow * H_DIM + (k - E_DIM)];
        sW[k * WT_ST + c] = w;
    }
    if (tid < BT) sLen[tid] = lengths[b0 + tid];
    if (gc == 0) {
        for (int idx = tid; idx < BT * H_DIM; idx += NTHR) {
            int m = idx / H_DIM, u = idx % H_DIM;
            g_h[0][b0 + m][perm16(u)] = __float2half_rn(h0[(b0 + m) * H_DIM + u]);
        }
    }
    if (tid < BT) sTok[tid] = inp[b0 + tid];   // tokens for t = 0
    __syncthreads();
    if (tid == 0) {
        int mx = 0;
        for (int i = 0; i < BT; ++i) mx = max(mx, sLen[i]);
        sMax[0] = mx;
    }
    __syncthreads();
    const int ctaMax = sMax[0];
    const unsigned rdyOwn  = sRdyBase[gc];
    const unsigned consOwn = sConsBase[gc];

    const int lane = tid & 31, warp = tid >> 5;
    const int mg = warp >> 3;     // m16 tile (0..1)
    const int nq = warp & 7;      // n8 group = 2 units (0..7)
    const int q  = lane & 3;
    const bool evn = !(q & 1);

    // This thread's SINGLE cell: row (even: r, odd: r+8), unit 2*nq + (q>>1)
    const int rowT = (lane >> 2) + (evn ? 0 : 8);
    const int m    = mg * 16 + rowT;            // 0..31
    const int b    = b0 + m;
    const int mylen = lengths[b];
    const int ul   = nq * 2 + (q >> 1);         // unit within CTA slice (0..15)
    const int ugg  = gc * HS + ul;
    const int ugp  = perm16(ugg);
    float cc = c0[b * H_DIM + ugg];
    const float bi  = b_ih[0 * H_DIM + ugg] + b_hh[0 * H_DIM + ugg];
    const float bf  = b_ih[1 * H_DIM + ugg] + b_hh[1 * H_DIM + ugg];
    const float bg_ = b_ih[2 * H_DIM + ugg] + b_hh[2 * H_DIM + ugg];
    const float bo  = b_ih[3 * H_DIM + ugg] + b_hh[3 * H_DIM + ugg];
    float* outH = out + B_DIM * O_DIM + (size_t)b * H_DIM;
    float* outC = outH + (size_t)B_DIM * H_DIM;

    // ---- preload B fragments (fp16 pairs), FULL K, n8 per warp: 48 regs ----
    unsigned bw[NKT][2];
    #pragma unroll
    for (int kt = 0; kt < NKT; ++kt) {
        int k0 = kt * 16 + 2 * (lane & 3);
        int n = nq * 8 + (lane >> 2);
        bw[kt][0] = packh2(sW[k0 * WT_ST + n],       sW[(k0 + 1) * WT_ST + n]);
        bw[kt][1] = packh2(sW[(k0 + 8) * WT_ST + n], sW[(k0 + 9) * WT_ST + n]);
    }

    // prologue: embedding columns of sA for t = 0 (permuted fp16 store)
    #pragma unroll
    for (int rep = 0; rep < (BT * 32) / NTHR; ++rep) {
        int i4 = tid + rep * NTHR;
        int mm = i4 >> 5, qq = i4 & 31;
        float4 v = __ldg(reinterpret_cast<const float4*>(emb + (size_t)sTok[mm] * E_DIM) + qq);
        int c = 4 * qq, grp = c & ~15, u0 = (c & 15) >> 1;
        int p0 = 2 * (u0 & 3) + (u0 >> 2);
        int p1 = 2 * ((u0 + 1) & 3) + ((u0 + 1) >> 2);
        *(unsigned*)&sAh[mm * ACT_STH + grp + 2 * p0] = packh2(v.x, v.y);
        *(unsigned*)&sAh[mm * ACT_STH + grp + 2 * p1] = packh2(v.z, v.w);
    }
    // init barrier: h_0 + init visible group-wide
    __syncthreads();
    if (tid == 0) {
        gbar_arrive(gb, gen0 + 1u);
        gbar_wait(gb, gen0 + 1u);
    }
    __syncthreads();

    // prologue gather: h_0 -> sA, warps 0-1 (they own CP_WAIT in the loop)
    if (warp < 2) {
        #pragma unroll 8
        for (int r = 0; r < 16; ++r) {
            int mm = warp * 16 + r;
            unsigned dst = (unsigned)__cvta_generic_to_shared(
                (char*)sAh + mm * ACT_STB + 256 + lane * 16);
            CP_ASYNC16(dst, (const char*)&g_h[0][b0 + mm][0] + lane * 16);
        }
        CP_COMMIT();
    }

    const char* Arow  = (const char*)sAh + (mg * 16 + (lane >> 2)) * ACT_STB + 8 * (lane & 3);
    const char* Arow8 = Arow + 8 * ACT_STB;

    // ---- recurrence: pipelined dataflow; h gather issued in previous tail ----
    for (int t = 0; t < ctaMax; ++t) {
        // prefetch next tokens (independent)
        if (tid < BT && t + 1 < ctaMax) sTok[tid] = inp[(t + 1) * B_DIM + b0 + tid];

        // phase 1: x-part GEMM; two independent acc chains (even/odd kt)
        float accA[4] = {}, accB[4] = {};
        #pragma unroll
        for (int kt = 0; kt < NXT; ++kt) {
            uint2 v0 = *(const uint2*)(Arow  + kt * 32);
            uint2 v1 = *(const uint2*)(Arow8 + kt * 32);
            if (kt & 1)
                mma16(accB[0], accB[1], accB[2], accB[3],
                      v0.x, v1.x, v0.y, v1.y, bw[kt][0], bw[kt][1]);
            else
                mma16(accA[0], accA[1], accA[2], accA[3],
                      v0.x, v1.x, v0.y, v1.y, bw[kt][0], bw[kt][1]);
        }
        if (warp < 2) CP_WAIT0();             // gather owners drain their groups
        __syncthreads();                      // sync1: h_t visible CTA-wide
        // our gather of h_t is complete -> release the ring slot
        if (tid == 0) st_rel(&g_cons[gb][gc][0], consOwn + (unsigned)t + 1u);

        // phase 2: h-part GEMM (k16-tiles 8..23)
        #pragma unroll
        for (int kt = NXT; kt < NKT; ++kt) {
            uint2 v0 = *(const uint2*)(Arow  + kt * 32);
            uint2 v1 = *(const uint2*)(Arow8 + kt * 32);
            if (kt & 1)
                mma16(accB[0], accB[1], accB[2], accB[3],
                      v0.x, v1.x, v0.y, v1.y, bw[kt][0], bw[kt][1]);
            else
                mma16(accA[0], accA[1], accA[2], accA[3],
                      v0.x, v1.x, v0.y, v1.y, bw[kt][0], bw[kt][1]);
        }

        // phase 3: IN-REGISTER elementwise, ONE cell per thread.
        const int wr = (t + 1) & (HD - 1);
        {
            float a0 = accA[0] + accB[0];
            float a1 = accA[1] + accB[1];
            float a2 = accA[2] + accB[2];
            float a3 = accA[3] + accB[3];
            float sA_ = __shfl_xor_sync(0xffffffffu, evn ? a2 : a0, 1);
            float sB_ = __shfl_xor_sync(0xffffffffu, evn ? a3 : a1, 1);
            float xi = (evn ? a0 : sA_) + bi;
            float xf = (evn ? a1 : sB_) + bf;
            float xg = (evn ? sA_ : a2) + bg_;
            float xo = (evn ? sB_ : a3) + bo;
            float ii = sigf(xi), ff = sigf(xf), gg = tanhfast(xg), oo = sigf(xo);
            float c = ff * cc + ii * gg;
            cc = c;
            float h = oo * tanhfast(c);
            g_h[wr][b][ugp] = __float2half_rn(h);
            if (t == mylen - 1) {
                outH[ugg] = h;                // last_h snapshot
                outC[ugg] = c;                // last_c snapshot
            }
        }
        __syncthreads();                      // sync3: all h STG issued CTA-wide
        // publish h_{t+1}
        if (tid == 0) st_rel(&g_ready[gb][gc][0], rdyOwn + (unsigned)t + 1u);

        // tail: warps 0-1 poll flags then each issues half the h_{t+1} gather;
        // warps 2-15 prefill next embeddings.
        if (t + 1 < ctaMax) {
            if (warp < 2) {
                unsigned i = lane & 15;
                const unsigned* ptr = (lane < 16) ? &g_ready[gb][i][0] : &g_cons[gb][i][0];
                int dcons = t + 3 - HD; if (dcons < 0) dcons = 0;
                unsigned tgt = (lane < 16) ? (sRdyBase[i] + (unsigned)(t + 1))
                                           : (sConsBase[i] + (unsigned)dcons);
                bool ok = false;
                do {
                    if (!ok) ok = ((int)(ld_acq(ptr) - tgt) >= 0);
                } while (!__all_sync(0xffffffffu, ok));
                // all peers published h_{t+1} and slot is safe: gather our half
                const int rs = (t + 1) & (HD - 1);
                #pragma unroll 8
                for (int r = 0; r < 16; ++r) {
                    int mm = warp * 16 + r;
                    unsigned dst = (unsigned)__cvta_generic_to_shared(
                        (char*)sAh + mm * ACT_STB + 256 + lane * 16);
                    CP_ASYNC16(dst, (const char*)&g_h[rs][b0 + mm][0] + lane * 16);
                }
                CP_COMMIT();
            } else {
                for (int i4 = tid - 64; i4 < BT * 32; i4 += NTHR - 64) {
                    int mm = i4 >> 5, qq = i4 & 31;
                    float4 v = __ldg(reinterpret_cast<const float4*>(emb + (size_t)sTok[mm] * E_DIM) + qq);
                    int c = 4 * qq, grp = c & ~15, u0 = (c & 15) >> 1;
                    int p0 = 2 * (u0 & 3) + (u0 >> 2);
                    int p1 = 2 * ((u0 + 1) & 3) + ((u0 + 1) >> 2);
                    *(unsigned*)&sAh[mm * ACT_STH + grp + 2 * p0] = packh2(v.x, v.y);
                    *(unsigned*)&sAh[mm * ACT_STH + grp + 2 * p1] = packh2(v.z, v.w);
                }
            }
        }
        __syncthreads();                      // sync4: prefill visible; gather in flight
    }

    // final join: all snapshots visible before the decoder
    if (tid == 0) {
        gbar_arrive(gb, gen0 + 2u);
        gbar_wait(gb, gen0 + 2u);
    }
    __syncthreads();

    // ---- decoder: decoded[b][o] = sigmoid(last_h[b] . dec_w[o]) ----
    if (gc == 0 && tid < 256) {
        int pair = tid >> 2, part = tid & 3;   // 64 (b,o) pairs x 4-way split-k
        int mm = pair >> 1, o = pair & 1;
        int bb = b0 + mm;
        const float* hrow = out + B_DIM * O_DIM + (size_t)bb * H_DIM;
        const float* wrow = dec_w + o * H_DIM;
        float s = 0.f;
        #pragma unroll 16
        for (int u = part * 64; u < part * 64 + 64; ++u)
            s += __ldcg(hrow + u) * wrow[u];
        s += __shfl_xor_sync(0xffffffffu, s, 1);
        s += __shfl_xor_sync(0xffffffffu, s, 2);
        if (part == 0) out[bb * O_DIM + o] = 1.0f / (1.0f + __expf(-s));
    }
}

extern "C" void kernel_launch(void* const* d_in, const int* in_sizes, int n_in,
                              void* d_out, int out_size) {
    const int*   inp = (const int*)d_in[0];
    const int*   len = (const int*)d_in[1];
    const float* h0  = (const float*)d_in[2];
    const float* c0  = (const float*)d_in[3];
    const float* emb = (const float*)d_in[4];
    const float* wih = (const float*)d_in[5];
    const float* whh = (const float*)d_in[6];
    const float* bih = (const float*)d_in[7];
    const float* bhh = (const float*)d_in[8];
    const float* dw  = (const float*)d_in[9];
    float* out = (float*)d_out;

    cudaFuncSetAttribute(lstm_kernel, cudaFuncAttributeMaxDynamicSharedMemorySize, SMEM_BYTES);
    lstm_kernel<<<NCTA, NTHR, SMEM_BYTES>>>(inp, len, h0, c0, emb, wih, whh, bih, bhh, dw, out);
}

// round 15
// speedup vs baseline: 1.4017x; 1.4017x over previous
#include <cuda_runtime.h>
#include <cuda_fp16.h>
#include <cstdint>

// Problem dims
#define S_LEN 1024
#define B_DIM 256
#define E_DIM 128
#define H_DIM 256
#define O_DIM 2
#define K_DIM (E_DIM + H_DIM)   // 384

// Decomposition: 16 batch groups x 8 hidden groups = 128 CTAs (1 per SM)
#define GB 16
#define GC 8
#define NCTA (GB * GC)
#define BT (B_DIM / GB)          // 16 batch rows per CTA
#define HS (H_DIM / GC)          // 32 hidden units per CTA
#define GT (4 * HS)              // 128 gate columns per CTA
#define NTHR 256

// fp16 GEMM, no k-split: 8 warps = 1 m16 tile x 8 n16 groups, full K per warp.
#define NKT 24                   // k16 tiles total (384/16)
#define NXT 8                    // x-part k16 tiles (emb, k<128)

// Hidden-state ring depth (producer/consumer slack)
#define HD 4

// Strides
#define WT_ST 136                // f32 weight [k][col] stride (init only), >= GT
#define ACT_STH 392              // sA row stride in halves (2-wavefront LDS.64 banking)
#define ACT_STB (ACT_STH * 2)    // 784 bytes

// SMEM byte layout. sW (init-only) OVERLAYS sA: sW is consumed by the
// B-fragment preload before the first sA write (guarded by __syncthreads).
#define OFF_W    0
#define OFF_A    0
#define W_BYTES  (K_DIM * WT_ST * 4)          // 208896
#define OFF_LEN  (W_BYTES)
#define OFF_TOK  (OFF_LEN + BT * 4)
#define OFF_MAX  (OFF_TOK + BT * 4)
#define OFF_RDY  (OFF_MAX + 16)
#define OFF_CONS (OFF_RDY + 64)
#define SMEM_BYTES (OFF_CONS + 64)
static_assert(BT * ACT_STB <= W_BYTES, "sA must fit under sW overlay");
static_assert(SMEM_BYTES <= 227 * 1024, "smem too big");

// Global scratch: ring-buffered hidden state, fp16, pair-permuted columns
__device__ __half g_h[HD][B_DIM][H_DIM];
// Init/final barrier (monotonic gen, replay-safe)
__device__ unsigned g_cnt[GB][32];
__device__ unsigned g_gen[GB][32];
// Dataflow flags: per-CTA monotonic counters, one 128B line each (R11 protocol)
__device__ unsigned g_ready[GB][GC][32];
__device__ unsigned g_cons[GB][GC][32];

// Pair permutation within each 16-col group: (col 2d,2d+1)+(2d+8,2d+9) adjacent -> LDS.64
__device__ __forceinline__ int perm16(int c) {
    int u = (c & 15) >> 1;
    int p = 2 * (u & 3) + (u >> 2);
    return (c & ~15) + 2 * p + (c & 1);
}

__device__ __forceinline__ float sigf(float x) {
    return __fdividef(1.0f, 1.0f + __expf(-x));
}
__device__ __forceinline__ float tanhfast(float x) {
    return 2.0f * __fdividef(1.0f, 1.0f + __expf(-2.0f * x)) - 1.0f;
}
__device__ __forceinline__ unsigned packh2(float a, float b) {
    __half2 h = __floats2half2_rn(a, b);
    return *reinterpret_cast<unsigned*>(&h);
}

__device__ __forceinline__ void mma16(float& d0, float& d1, float& d2, float& d3,
                                      unsigned a0, unsigned a1, unsigned a2, unsigned a3,
                                      unsigned b0, unsigned b1) {
    asm volatile(
        "mma.sync.aligned.m16n8k16.row.col.f32.f16.f16.f32 "
        "{%0,%1,%2,%3},{%4,%5,%6,%7},{%8,%9},{%0,%1,%2,%3};"
        : "+f"(d0), "+f"(d1), "+f"(d2), "+f"(d3)
        : "r"(a0), "r"(a1), "r"(a2), "r"(a3), "r"(b0), "r"(b1));
}

#define CP_ASYNC16(dst_u32, src) \
    asm volatile("cp.async.cg.shared.global [%0], [%1], 16;" :: "r"(dst_u32), "l"(src))
#define CP_COMMIT() asm volatile("cp.async.commit_group;")
#define CP_WAIT0()  asm volatile("cp.async.wait_group 0;")

__device__ __forceinline__ unsigned ld_acq(const unsigned* p) {
    unsigned v;
    asm volatile("ld.acquire.gpu.global.u32 %0, [%1];" : "=r"(v) : "l"(p) : "memory");
    return v;
}
__device__ __forceinline__ void st_rel(unsigned* p, unsigned v) {
    asm volatile("st.release.gpu.global.u32 [%0], %1;" :: "l"(p), "r"(v) : "memory");
}

__device__ __forceinline__ void gbar_arrive(int gb, unsigned target) {
    unsigned old;
    asm volatile("atom.acq_rel.gpu.global.add.u32 %0, [%1], %2;"
                 : "=r"(old) : "l"(&g_cnt[gb][0]), "r"(1u) : "memory");
    if (old == GC - 1u) {
        asm volatile("st.relaxed.gpu.global.u32 [%0], %1;" :: "l"(&g_cnt[gb][0]), "r"(0u) : "memory");
        st_rel(&g_gen[gb][0], target);
    }
}
__device__ __forceinline__ void gbar_wait(int gb, unsigned target) {
    while ((int)(ld_acq(&g_gen[gb][0]) - target) < 0) {}
}

__global__ void __launch_bounds__(NTHR, 1)
lstm_kernel(const int* __restrict__ inp, const int* __restrict__ lengths,
            const float* __restrict__ h0, const float* __restrict__ c0,
            const float* __restrict__ emb, const float* __restrict__ w_ih,
            const float* __restrict__ w_hh, const float* __restrict__ b_ih,
            const float* __restrict__ b_hh, const float* __restrict__ dec_w,
            float* __restrict__ out) {
    extern __shared__ char smc[];
    float*    sW    = (float*)(smc + OFF_W);      // [K_DIM][WT_ST] f32, INIT ONLY
    __half*   sAh   = (__half*)(smc + OFF_A);     // [BT][ACT_STH] (overlays sW after init)
    int*      sLen  = (int*)(smc + OFF_LEN);      // [BT]
    int*      sTok  = (int*)(smc + OFF_TOK);      // [BT]
    int*      sMax  = (int*)(smc + OFF_MAX);      // [1]
    unsigned* sRdyBase  = (unsigned*)(smc + OFF_RDY);   // [GC]
    unsigned* sConsBase = (unsigned*)(smc + OFF_CONS);  // [GC]

    const int tid = threadIdx.x;
    const int cta = blockIdx.x;
    const int gb = cta / GC;
    const int gc = cta % GC;
    const int b0 = gb * BT;

    // --- entry sampling (race-free before the init barrier) ---
    unsigned gen0 = 0;
    if (tid == 0) gen0 = ld_acq(&g_gen[gb][0]);
    if (tid < GC) {
        sRdyBase[tid]  = ld_acq(&g_ready[gb][tid][0]);
        sConsBase[tid] = ld_acq(&g_cons[gb][tid][0]);
    }

    // ---- one-time init ----
    // Weight columns GATE-INTERLEAVED: col = 4*unit_local + gate (i,f,g,o)
    for (int idx = tid; idx < K_DIM * GT; idx += NTHR) {
        int k = idx / GT, c = idx % GT;
        int unit = c >> 2, gate = c & 3;
        int grow = gate * H_DIM + gc * HS + unit;
        float w = (k < E_DIM) ? w_ih[grow * E_DIM + k] : w_hh[grow * H_DIM + (k - E_DIM)];
        sW[k * WT_ST + c] = w;
    }
    if (tid < BT) sLen[tid] = lengths[b0 + tid];
    if (gc == 0) {
        for (int idx = tid; idx < BT * H_DIM; idx += NTHR) {
            int m = idx / H_DIM, u = idx % H_DIM;
            g_h[0][b0 + m][perm16(u)] = __float2half_rn(h0[(b0 + m) * H_DIM + u]);
        }
    }
    if (tid < BT) sTok[tid] = inp[b0 + tid];   // tokens for t = 0
    __syncthreads();
    if (tid == 0) {
        int mx = 0;
        for (int i = 0; i < BT; ++i) mx = max(mx, sLen[i]);
        sMax[0] = mx;
    }
    __syncthreads();
    const int ctaMax = sMax[0];
    const unsigned rdyOwn  = sRdyBase[gc];
    const unsigned consOwn = sConsBase[gc];

    const int lane = tid & 31, warp = tid >> 5;
    const int nq = warp;          // n16 group = 4 units (0..7)
    const int q  = lane & 3;
    const bool evn = !(q & 1);

    // This thread's 2 cells: row (even: r, odd: r+8), units nq*4 + 2j + (q>>1)
    const int m    = (lane >> 2) + (evn ? 0 : 8);   // 0..15
    const int b    = b0 + m;
    const int mylen = lengths[b];
    int   ugg[2];  // global unit index per j
    int   ugp[2];  // permuted (for g_h)
    float cc[2];   // cell state in registers
    float bi[2], bf[2], bg_[2], bo[2];
    #pragma unroll
    for (int j = 0; j < 2; ++j) {
        int ul = nq * 4 + 2 * j + (q >> 1);     // unit within CTA slice (0..31)
        ugg[j] = gc * HS + ul;
        ugp[j] = perm16(ugg[j]);
        cc[j]  = c0[b * H_DIM + ugg[j]];
        bi[j]  = b_ih[0 * H_DIM + ugg[j]] + b_hh[0 * H_DIM + ugg[j]];
        bf[j]  = b_ih[1 * H_DIM + ugg[j]] + b_hh[1 * H_DIM + ugg[j]];
        bg_[j] = b_ih[2 * H_DIM + ugg[j]] + b_hh[2 * H_DIM + ugg[j]];
        bo[j]  = b_ih[3 * H_DIM + ugg[j]] + b_hh[3 * H_DIM + ugg[j]];
    }
    float* outH = out + B_DIM * O_DIM + (size_t)b * H_DIM;
    float* outC = outH + (size_t)B_DIM * H_DIM;

    // ---- preload B fragments (fp16 pairs), FULL K, n16 per warp: 96 regs ----
    unsigned bw[NKT][2][2];
    #pragma unroll
    for (int kt = 0; kt < NKT; ++kt) {
        int k0 = kt * 16 + 2 * (lane & 3);
        #pragma unroll
        for (int j = 0; j < 2; ++j) {
            int n = nq * 16 + j * 8 + (lane >> 2);
            bw[kt][j][0] = packh2(sW[k0 * WT_ST + n],       sW[(k0 + 1) * WT_ST + n]);
            bw[kt][j][1] = packh2(sW[(k0 + 8) * WT_ST + n], sW[(k0 + 9) * WT_ST + n]);
        }
    }
    __syncthreads();   // sW fully consumed before sA overlays it

    // prologue: embedding columns of sA for t = 0 (permuted fp16 store)
    #pragma unroll
    for (int rep = 0; rep < (BT * 32) / NTHR; ++rep) {
        int i4 = tid + rep * NTHR;
        int mm = i4 >> 5, qq = i4 & 31;
        float4 v = __ldg(reinterpret_cast<const float4*>(emb + (size_t)sTok[mm] * E_DIM) + qq);
        int c = 4 * qq, grp = c & ~15, u0 = (c & 15) >> 1;
        int p0 = 2 * (u0 & 3) + (u0 >> 2);
        int p1 = 2 * ((u0 + 1) & 3) + ((u0 + 1) >> 2);
        *(unsigned*)&sAh[mm * ACT_STH + grp + 2 * p0] = packh2(v.x, v.y);
        *(unsigned*)&sAh[mm * ACT_STH + grp + 2 * p1] = packh2(v.z, v.w);
    }
    // init barrier: h_0 + init visible group-wide
    __syncthreads();
    if (tid == 0) {
        gbar_arrive(gb, gen0 + 1u);
        gbar_wait(gb, gen0 + 1u);
    }
    __syncthreads();

    // prologue gather: h_0 -> sA, warps 0-1 (they own CP_WAIT), 8 rows each
    if (warp < 2) {
        #pragma unroll 8
        for (int r = 0; r < 8; ++r) {
            int mm = warp * 8 + r;
            unsigned dst = (unsigned)__cvta_generic_to_shared(
                (char*)sAh + mm * ACT_STB + 256 + lane * 16);
            CP_ASYNC16(dst, (const char*)&g_h[0][b0 + mm][0] + lane * 16);
        }
        CP_COMMIT();
    }

    const char* Arow  = (const char*)sAh + (lane >> 2) * ACT_STB + 8 * (lane & 3);
    const char* Arow8 = Arow + 8 * ACT_STB;

    // ---- recurrence: pipelined dataflow; h gather issued in previous tail ----
    for (int t = 0; t < ctaMax; ++t) {
        // prefetch next tokens (independent)
        if (tid < BT && t + 1 < ctaMax) sTok[tid] = inp[(t + 1) * B_DIM + b0 + tid];

        // phase 1: x-part GEMM (h gather from previous tail still landing)
        float acc[2][4] = {};
        #pragma unroll
        for (int kt = 0; kt < NXT; ++kt) {
            uint2 v0 = *(const uint2*)(Arow  + kt * 32);
            uint2 v1 = *(const uint2*)(Arow8 + kt * 32);
            #pragma unroll
            for (int j = 0; j < 2; ++j)
                mma16(acc[j][0], acc[j][1], acc[j][2], acc[j][3],
                      v0.x, v1.x, v0.y, v1.y, bw[kt][j][0], bw[kt][j][1]);
        }
        if (warp < 2) CP_WAIT0();             // gather owners drain their groups
        __syncthreads();                      // sync1: h_t visible CTA-wide
        // our gather of h_t is complete -> release the ring slot
        if (tid == 0) st_rel(&g_cons[gb][gc][0], consOwn + (unsigned)t + 1u);

        // phase 2: h-part GEMM (k16-tiles 8..23)
        #pragma unroll
        for (int kt = NXT; kt < NKT; ++kt) {
            uint2 v0 = *(const uint2*)(Arow  + kt * 32);
            uint2 v1 = *(const uint2*)(Arow8 + kt * 32);
            #pragma unroll
            for (int j = 0; j < 2; ++j)
                mma16(acc[j][0], acc[j][1], acc[j][2], acc[j][3],
                      v0.x, v1.x, v0.y, v1.y, bw[kt][j][0], bw[kt][j][1]);
        }

        // phase 3: IN-REGISTER elementwise. Lane-pair shuffle completes gates.
        const int wr = (t + 1) & (HD - 1);
        #pragma unroll
        for (int j = 0; j < 2; ++j) {
            float sA_ = __shfl_xor_sync(0xffffffffu, evn ? acc[j][2] : acc[j][0], 1);
            float sB_ = __shfl_xor_sync(0xffffffffu, evn ? acc[j][3] : acc[j][1], 1);
            float xi = (evn ? acc[j][0] : sA_) + bi[j];
            float xf = (evn ? acc[j][1] : sB_) + bf[j];
            float xg = (evn ? sA_ : acc[j][2]) + bg_[j];
            float xo = (evn ? sB_ : acc[j][3]) + bo[j];
            float ii = sigf(xi), ff = sigf(xf), gg = tanhfast(xg), oo = sigf(xo);
            float c = ff * cc[j] + ii * gg;
            cc[j] = c;
            float h = oo * tanhfast(c);
            g_h[wr][b][ugp[j]] = __float2half_rn(h);
            if (t == mylen - 1) {
                outH[ugg[j]] = h;             // last_h snapshot
                outC[ugg[j]] = c;             // last_c snapshot
            }
        }
        __syncthreads();                      // sync3: all h STG issued CTA-wide
        // publish h_{t+1}
        if (tid == 0) st_rel(&g_ready[gb][gc][0], rdyOwn + (unsigned)t + 1u);

        // tail: warps 0-1 poll flags then each issues half the h_{t+1} gather;
        // warps 2-7 prefill next embeddings.
        if (t + 1 < ctaMax) {
            if (warp < 2) {
                const unsigned* ptr = &g_ready[gb][0][0];  // default lane 0 target
                unsigned tgt = 0;
                bool active = false;
                if (lane < GC) {
                    ptr = &g_ready[gb][lane][0];
                    tgt = sRdyBase[lane] + (unsigned)(t + 1);
                    active = true;
                } else if (lane >= 16 && lane < 16 + GC) {
                    int dcons = t + 3 - HD; if (dcons < 0) dcons = 0;
                    ptr = &g_cons[gb][lane - 16][0];
                    tgt = sConsBase[lane - 16] + (unsigned)dcons;
                    active = true;
                }
                bool ok = !active;
                do {
                    if (!ok) ok = ((int)(ld_acq(ptr) - tgt) >= 0);
                } while (!__all_sync(0xffffffffu, ok));
                // all peers published h_{t+1} and slot is safe: gather our half
                const int rs = (t + 1) & (HD - 1);
                #pragma unroll 8
                for (int r = 0; r < 8; ++r) {
                    int mm = warp * 8 + r;
                    unsigned dst = (unsigned)__cvta_generic_to_shared(
                        (char*)sAh + mm * ACT_STB + 256 + lane * 16);
                    CP_ASYNC16(dst, (const char*)&g_h[rs][b0 + mm][0] + lane * 16);
                }
                CP_COMMIT();
            } else {
                for (int i4 = tid - 64; i4 < BT * 32; i4 += NTHR - 64) {
                    int mm = i4 >> 5, qq = i4 & 31;
                    float4 v = __ldg(reinterpret_cast<const float4*>(emb + (size_t)sTok[mm] * E_DIM) + qq);
                    int c = 4 * qq, grp = c & ~15, u0 = (c & 15) >> 1;
                    int p0 = 2 * (u0 & 3) + (u0 >> 2);
                    int p1 = 2 * ((u0 + 1) & 3) + ((u0 + 1) >> 2);
                    *(unsigned*)&sAh[mm * ACT_STH + grp + 2 * p0] = packh2(v.x, v.y);
                    *(unsigned*)&sAh[mm * ACT_STH + grp + 2 * p1] = packh2(v.z, v.w);
                }
            }
        }
        __syncthreads();                      // sync4: prefill visible; gather in flight
    }

    // final join: all snapshots visible before the decoder
    if (tid == 0) {
        gbar_arrive(gb, gen0 + 2u);
        gbar_wait(gb, gen0 + 2u);
    }
    __syncthreads();

    // ---- decoder: decoded[b][o] = sigmoid(last_h[b] . dec_w[o]) ----
    if (gc == 0) {
        int pair = tid >> 3, part = tid & 7;   // 32 (b,o) pairs x 8-way split-k
        int mm = pair >> 1, o = pair & 1;
        int bb = b0 + mm;
        const float* hrow = out + B_DIM * O_DIM + (size_t)bb * H_DIM;
        const float* wrow = dec_w + o * H_DIM;
        float s = 0.f;
        #pragma unroll 8
        for (int u = part * 32; u < part * 32 + 32; ++u)
            s += __ldcg(hrow + u) * wrow[u];
        s += __shfl_xor_sync(0xffffffffu, s, 1);
        s += __shfl_xor_sync(0xffffffffu, s, 2);
        s += __shfl_xor_sync(0xffffffffu, s, 4);
        if (part == 0) out[bb * O_DIM + o] = 1.0f / (1.0f + __expf(-s));
    }
}

extern "C" void kernel_launch(void* const* d_in, const int* in_sizes, int n_in,
                              void* d_out, int out_size) {
    const int*   inp = (const int*)d_in[0];
    const int*   len = (const int*)d_in[1];
    const float* h0  = (const float*)d_in[2];
    const float* c0  = (const float*)d_in[3];
    const float* emb = (const float*)d_in[4];
    const float* wih = (const float*)d_in[5];
    const float* whh = (const float*)d_in[6];
    const float* bih = (const float*)d_in[7];
    const float* bhh = (const float*)d_in[8];
    const float* dw  = (const float*)d_in[9];
    float* out = (float*)d_out;

    cudaFuncSetAttribute(lstm_kernel, cudaFuncAttributeMaxDynamicSharedMemorySize, SMEM_BYTES);
    lstm_kernel<<<NCTA, NTHR, SMEM_BYTES>>>(inp, len, h0, c0, emb, wih, whh, bih, bhh, dw, out);
}